// round 1
// baseline (speedup 1.0000x reference)
#include <cuda_runtime.h>
#include <math.h>

#define NCELLS 131072
#define HID 128
#define OUTD 64
#define TC 64                 // cells per block
#define NBLK (NCELLS / TC)    // 2048
#define BT 128                // threads per block
#define XP 68                 // pitch (floats) for activation buffers, cell-minor
#define WP 132                // pitch (floats) for weight buffer, neuron-minor

// ---- dynamic smem layout (float offsets) ----
#define OFF_HT   0                      // hT   [128][XP]  h transposed (dim-major)
#define OFF_W    (OFF_HT + 128 * XP)    // Wbuf [<=128][WP]
#define OFF_ACT  (OFF_W + 128 * WP)     // actT / rT / izT [128][XP]
#define OFF_OUT  (OFF_ACT + 128 * XP)   // outT [65][XP] (row 64 = tension t)
#define OFF_IN   (OFF_OUT + 65 * XP)    // i_n then n [128][XP]
#define OFF_PART (OFF_IN + 128 * XP)    // faction partial sums [128]
#define OFF_RED  (OFF_PART + 128)       // e[64], t[64]
#define SMEM_FLOATS (OFF_RED + 192)
#define SMEM_BYTES (SMEM_FLOATS * 4)

// ---- scratch (device globals; no allocation allowed) ----
__device__ float g_newh[NCELLS * HID];       // pre-faction-sync new_h (64 MB)
__device__ float g_pfm[NBLK * HID];          // per-block column sums of new_h
__device__ float g_peout[NBLK * OUTD];       // per-block sum of exp(t)*out
__device__ float g_pe[NBLK];                 // per-block sum exp(t)
__device__ float g_pt[NBLK];                 // per-block sum t
__device__ float g_v1[256];                  // v1a[128], v1g[128] = W1[:, :64]@x + b1
__device__ float g_fm[8 * HID];              // faction means
__device__ float g_go[HID];                  // global opinion

__device__ __forceinline__ float sigmoidf_(float v) { return 1.0f / (1.0f + expf(-v)); }

// ============================================================================
// Fused GEMM stage: Y[NCH neurons x TC cells] = W[NCH x K] @ X[K x TC] + bias
// X is staged in smem k-major (pitch XP). W chunk loaded coalesced into smem
// transposed (k-major, pitch WP). 8 cells x (NCH/16) neurons per thread.
// MODE: 0=STORE 1=RELU 2=SUB(Y-=acc) 3=Y=sig(Y+acc) 4=Y=tanh(Y + rT*acc)
//       5=FINAL (z=sig(izT+acc); newh=(1-z)*nT + z*hT -> gmem + faction part.)
// ============================================================================
template <int K, int NCH, int MODE>
__device__ __forceinline__ void gemm_stage(
    float* sm, const float* __restrict__ W, int ldW,
    const float* __restrict__ bias, int xoff, int yoff, int cell0) {
  const int t = threadIdx.x;
  float* Wb = sm + OFF_W;
  __syncthreads();   // protect Wbuf + make prior-stage writes visible
  for (int idx = t; idx < NCH * K; idx += BT) {
    int n = idx / K;
    int k = idx - n * K;
    Wb[k * WP + n] = W[n * ldW + k];   // coalesced global read, strided smem write
  }
  __syncthreads();

  constexpr int NP = NCH / 16;   // 8 (NCH=128) or 4 (NCH=64)
  const int cg = t & 7;          // 8 cell-groups of 8 cells
  const int ng = t >> 3;         // 16 neuron-groups of NP neurons
  float bv[NP];
#pragma unroll
  for (int ni = 0; ni < NP; ni++) bv[ni] = bias[ng * NP + ni];
  float acc[8][NP];
#pragma unroll
  for (int ci = 0; ci < 8; ci++)
#pragma unroll
    for (int ni = 0; ni < NP; ni++) acc[ci][ni] = bv[ni];

  const float* X = sm + xoff + 8 * cg;
  const float* Wr = Wb + NP * ng;
#pragma unroll 4
  for (int k = 0; k < K; k++) {
    float4 xa = *(const float4*)(X + k * XP);
    float4 xb = *(const float4*)(X + k * XP + 4);
    float x[8] = {xa.x, xa.y, xa.z, xa.w, xb.x, xb.y, xb.z, xb.w};
    float w[NP];
    float4 wa = *(const float4*)(Wr + k * WP);
    w[0] = wa.x; w[1] = wa.y; w[2] = wa.z; w[3] = wa.w;
    if constexpr (NP == 8) {
      float4 wb = *(const float4*)(Wr + k * WP + 4);
      w[4] = wb.x; w[5] = wb.y; w[6] = wb.z; w[7] = wb.w;
    }
#pragma unroll
    for (int ci = 0; ci < 8; ci++)
#pragma unroll
      for (int ni = 0; ni < NP; ni++) acc[ci][ni] = fmaf(x[ci], w[ni], acc[ci][ni]);
  }

  float* Y = sm + yoff;
  float* rT = sm + OFF_ACT;
  float* inT = sm + OFF_IN;
  float* hT = sm + OFF_HT;
  float* part = sm + OFF_PART;

  if constexpr (MODE <= 4) {
#pragma unroll
    for (int ni = 0; ni < NP; ni++) {
      int n = ng * NP + ni;
#pragma unroll
      for (int ci = 0; ci < 8; ci++) {
        int c = cg * 8 + ci;
        int idx = n * XP + c;
        float v = acc[ci][ni];
        if constexpr (MODE == 0) Y[idx] = v;
        else if constexpr (MODE == 1) Y[idx] = fmaxf(v, 0.0f);
        else if constexpr (MODE == 2) Y[idx] = Y[idx] - v;
        else if constexpr (MODE == 3) Y[idx] = sigmoidf_(Y[idx] + v);
        else if constexpr (MODE == 4) Y[idx] = tanhf(Y[idx] + rT[idx] * v);
      }
    }
  } else {
    // FINAL: acc = hz(+bhh). z = sigmoid(iz + hz); newh = (1-z)*n + z*h
    float nsum[8];
#pragma unroll
    for (int ni = 0; ni < 8; ni++) nsum[ni] = 0.0f;
#pragma unroll
    for (int ci = 0; ci < 8; ci++) {
      int c = cg * 8 + ci;
      float vals[8];
#pragma unroll
      for (int ni = 0; ni < 8; ni++) {
        int n = ng * 8 + ni;
        int idx = n * XP + c;
        float z = sigmoidf_(rT[idx] + acc[ci][ni]);   // rT holds iz here
        float nh = (1.0f - z) * inT[idx] + z * hT[idx];
        vals[ni] = nh;
        nsum[ni] += nh;
      }
      float4 a = make_float4(vals[0], vals[1], vals[2], vals[3]);
      float4 b = make_float4(vals[4], vals[5], vals[6], vals[7]);
      float4* dst = (float4*)(g_newh + (size_t)(cell0 + c) * HID + ng * 8);
      dst[0] = a;
      dst[1] = b;
    }
#pragma unroll
    for (int ni = 0; ni < 8; ni++) atomicAdd(&part[ng * 8 + ni], nsum[ni]);
  }
}

// ============================================================================
// K0: v1a/v1g = W1[:, :64] @ x + b1  (x is shared by all cells)
// ============================================================================
__global__ void k0(const float* __restrict__ x,
                   const float* __restrict__ W1a, const float* __restrict__ b1a,
                   const float* __restrict__ W1g, const float* __restrict__ b1g) {
  __shared__ float xs[64];
  int t = threadIdx.x;
  if (t < 64) xs[t] = x[t];
  __syncthreads();
  const float* W = (t < 128) ? W1a : W1g;
  const float* b = (t < 128) ? b1a : b1g;
  int n = t & 127;
  float s = b[n];
#pragma unroll 8
  for (int k = 0; k < 64; k++) s = fmaf(W[n * 192 + k], xs[k], s);
  g_v1[t] = s;
}

// ============================================================================
// K1: fused engines + tension + GRU per 64-cell tile
// ============================================================================
__global__ void __launch_bounds__(BT, 1) k1(
    const float* __restrict__ hiddens,
    const float* __restrict__ W1a, const float* __restrict__ W2a, const float* __restrict__ b2a,
    const float* __restrict__ W1g, const float* __restrict__ W2g, const float* __restrict__ b2g,
    const float* __restrict__ Wih, const float* __restrict__ Whh,
    const float* __restrict__ bih, const float* __restrict__ bhh) {
  extern __shared__ float sm[];
  const int t = threadIdx.x;
  const int cell0 = blockIdx.x * TC;

  sm[OFF_PART + t] = 0.0f;

  // stage h transposed: hT[d][c]
  const float4* hsrc = (const float4*)(hiddens + (size_t)cell0 * HID);
  for (int i = t; i < TC * 32; i += BT) {
    int c = i >> 5;
    int dq = i & 31;
    float4 v = hsrc[c * 32 + dq];
    float* dst = sm + OFF_HT + (dq * 4) * XP + c;
    dst[0] = v.x; dst[XP] = v.y; dst[2 * XP] = v.z; dst[3 * XP] = v.w;
  }

  // engines (x-part folded into g_v1 bias)
  gemm_stage<128, 128, 1>(sm, W1a + 64, 192, g_v1,        OFF_HT,  OFF_ACT, cell0);
  gemm_stage<128,  64, 0>(sm, W2a,      128, b2a,         OFF_ACT, OFF_OUT, cell0);
  gemm_stage<128, 128, 1>(sm, W1g + 64, 192, g_v1 + 128,  OFF_HT,  OFF_ACT, cell0);
  gemm_stage<128,  64, 2>(sm, W2g,      128, b2g,         OFF_ACT, OFF_OUT, cell0);
  __syncthreads();

  // tension + softmax/pool partials
  float* outT = sm + OFF_OUT;
  float* esm = sm + OFF_RED;
  float* tsm = sm + OFF_RED + 64;
  if (t < TC) {
    float s = 0.0f;
#pragma unroll
    for (int d = 0; d < OUTD; d++) { float v = outT[d * XP + t]; s = fmaf(v, v, s); }
    float tc = s * (1.0f / OUTD);
    outT[64 * XP + t] = tc;      // gru_in last channel
    esm[t] = expf(tc);           // t in ~[0.3, 2.5]: no max-sub needed
    tsm[t] = tc;
  }
  __syncthreads();
  if (t < OUTD) {
    float s = 0.0f;
#pragma unroll
    for (int c = 0; c < TC; c++) s = fmaf(esm[c], outT[t * XP + c], s);
    g_peout[blockIdx.x * OUTD + t] = s;
  }
  if (t == 0) {
    float se = 0.0f, st = 0.0f;
#pragma unroll
    for (int c = 0; c < TC; c++) { se += esm[c]; st += tsm[c]; }
    g_pe[blockIdx.x] = se;
    g_pt[blockIdx.x] = st;
  }

  // GRU: r gate (summable), n gate (r * h-side only!), z gate fused with combine
  gemm_stage<65, 128, 0>(sm, Wih,             65, bih,       OFF_OUT, OFF_ACT, cell0); // ir
  gemm_stage<128, 128, 3>(sm, Whh,           128, bhh,       OFF_HT,  OFF_ACT, cell0); // r=sig(ir+hr)
  gemm_stage<65, 128, 0>(sm, Wih + 256 * 65,  65, bih + 256, OFF_OUT, OFF_IN,  cell0); // i_n
  gemm_stage<128, 128, 4>(sm, Whh + 256 * 128,128, bhh + 256,OFF_HT,  OFF_IN,  cell0); // n=tanh(i_n+r*h_n)
  gemm_stage<65, 128, 0>(sm, Wih + 128 * 65,  65, bih + 128, OFF_OUT, OFF_ACT, cell0); // iz
  gemm_stage<128, 128, 5>(sm, Whh + 128 * 128,128, bhh + 128,OFF_HT,  0,       cell0); // z + newh
  __syncthreads();

  g_pfm[blockIdx.x * HID + t] = sm[OFF_PART + t];
}

// ============================================================================
// K2: fixed-order reductions, faction means, global opinion, pooled head
// ============================================================================
__global__ void __launch_bounds__(256) k2(const float* __restrict__ Wo,
                                          const float* __restrict__ bo,
                                          float* __restrict__ d_out) {
  __shared__ float red[256];
  __shared__ float comb[64];
  __shared__ float sume_s;
  int t = threadIdx.x;

  for (int o = t; o < 8 * HID; o += 256) {       // faction means
    int f = o >> 7, d = o & 127;
    const float* p = g_pfm + (size_t)f * 256 * HID + d;
    float s = 0.0f;
#pragma unroll 8
    for (int b = 0; b < 256; b++) s += p[b * HID];
    g_fm[o] = s * (1.0f / 16384.0f);
  }
  __syncthreads();
  if (t < HID) {                                  // global opinion
    float s = 0.0f;
#pragma unroll
    for (int f = 0; f < 8; f++) s += g_fm[f * HID + t];
    g_go[t] = s * 0.125f;
  }

  float se = 0.0f, st = 0.0f;
  for (int b = t; b < NBLK; b += 256) { se += g_pe[b]; st += g_pt[b]; }
  red[t] = se;
  __syncthreads();
  for (int s2 = 128; s2 > 0; s2 >>= 1) { if (t < s2) red[t] += red[t + s2]; __syncthreads(); }
  if (t == 0) sume_s = red[0];
  __syncthreads();
  red[t] = st;
  __syncthreads();
  for (int s2 = 128; s2 > 0; s2 >>= 1) { if (t < s2) red[t] += red[t + s2]; __syncthreads(); }
  if (t == 0) d_out[64] = red[0] * (1.0f / NCELLS);   // t.mean()

  if (t < 64) {
    float s = 0.0f;
#pragma unroll 8
    for (int b = 0; b < NBLK; b++) s += g_peout[b * 64 + t];
    comb[t] = s / sume_s;                          // combined = softmax(t) @ out
  }
  __syncthreads();
  if (t < 64) {
    float s = bo[t];
#pragma unroll
    for (int d = 0; d < 64; d++) s = fmaf(Wo[t * 64 + d], comb[d], s);
    d_out[t] = s;                                  // pred
  }
}

// ============================================================================
// K3: apply faction sync + debate, stream to output
// ============================================================================
__global__ void __launch_bounds__(256) k3(const int* __restrict__ step,
                                          float* __restrict__ d_out) {
  int i = blockIdx.x * 256 + threadIdx.x;          // one float4 of new_h
  float4 nh = ((const float4*)g_newh)[i];
  int c = i >> 5;                                  // cell (32 float4 per cell)
  int dq = i & 31;
  int f = c >> 14;                                 // faction (16384 cells each)
  float4 fm4 = ((const float4*)g_fm)[f * 32 + dq];
  float4 v;
  v.x = 0.85f * nh.x + 0.15f * fm4.x;
  v.y = 0.85f * nh.y + 0.15f * fm4.y;
  v.z = 0.85f * nh.z + 0.15f * fm4.z;
  v.w = 0.85f * nh.w + 0.15f * fm4.w;
  if (((c & 16383) < 4096) && (*step > 5)) {
    float4 go4 = ((const float4*)g_go)[dq];
    v.x = 0.85f * v.x + 0.15f * go4.x;
    v.y = 0.85f * v.y + 0.15f * go4.y;
    v.z = 0.85f * v.z + 0.15f * go4.z;
    v.w = 0.85f * v.w + 0.15f * go4.w;
  }
  float* o = d_out + 65 + (size_t)i * 4;           // output offset 65 (pred + t_mean)
  o[0] = v.x; o[1] = v.y; o[2] = v.z; o[3] = v.w;
}

extern "C" void kernel_launch(void* const* d_in, const int* in_sizes, int n_in,
                              void* d_out, int out_size) {
  const float* x    = (const float*)d_in[0];
  const float* hid  = (const float*)d_in[1];
  const float* W1a  = (const float*)d_in[2];
  const float* b1a  = (const float*)d_in[3];
  const float* W2a  = (const float*)d_in[4];
  const float* b2a  = (const float*)d_in[5];
  const float* W1g  = (const float*)d_in[6];
  const float* b1g  = (const float*)d_in[7];
  const float* W2g  = (const float*)d_in[8];
  const float* b2g  = (const float*)d_in[9];
  const float* Wih  = (const float*)d_in[10];
  const float* Whh  = (const float*)d_in[11];
  const float* bih  = (const float*)d_in[12];
  const float* bhh  = (const float*)d_in[13];
  const float* Wo   = (const float*)d_in[14];
  const float* bo   = (const float*)d_in[15];
  const int* step   = (const int*)d_in[16];
  float* out = (float*)d_out;

  cudaFuncSetAttribute(k1, cudaFuncAttributeMaxDynamicSharedMemorySize, SMEM_BYTES);

  k0<<<1, 256>>>(x, W1a, b1a, W1g, b1g);
  k1<<<NBLK, BT, SMEM_BYTES>>>(hid, W1a, W2a, b2a, W1g, W2g, b2g, Wih, Whh, bih, bhh);
  k2<<<1, 256>>>(Wo, bo, out);
  k3<<<(NCELLS * HID / 4) / 256, 256>>>(step, out);
}

// round 2
// speedup vs baseline: 2.0435x; 2.0435x over previous
#include <cuda_runtime.h>
#include <math.h>
#include <stdint.h>

#define NCELLS 131072
#define HID 128
#define OUTD 64
#define TC 64                 // cells per block
#define NBLK (NCELLS / TC)    // 2048
#define BT 256                // threads per block (8 warps)

#define AP 132                // activation buffer pitch (floats)
#define OP 68                 // out buffer pitch (floats)

// ---- dynamic smem layout (float offsets) ----
#define OFF_H    0                       // h   [64][AP]  (rna tf32)
#define OFF_ACT  (OFF_H + 64 * AP)       // relu / ir / r / iz  [64][AP]
#define OFF_IN   (OFF_ACT + 64 * AP)     // i_n / n  [64][AP]
#define OFF_OUT  (OFF_IN + 64 * AP)      // out [64][OP] (col 64 = t)
#define OFF_W    (OFF_OUT + 64 * OP)     // weight stage buffer [<=128][<=132]
#define OFF_PART (OFF_W + 128 * 132)     // faction partials [128]
#define OFF_RED  (OFF_PART + 128)        // esm[64], tsm[64]
#define SMEM_FLOATS (OFF_RED + 128)
#define SMEM_BYTES (SMEM_FLOATS * 4)

// ---- packed weight image offsets (floats) ----
#define WO_S1  0        // W1a_h   128x132
#define WO_S2  16896    // W2a      64x132
#define WO_S3  25344    // W1g_h   128x132
#define WO_S4  42240    // W2g      64x132
#define WO_S5  50688    // Wih_r   128x68
#define WO_S6  59392    // Whh_r   128x132
#define WO_S7  76288    // Wih_n   128x68
#define WO_S8  84992    // Whh_n   128x132
#define WO_S9  101888   // Wih_z   128x68
#define WO_S10 110592   // Whh_z   128x132
#define WPACK_FLOATS 127488

// ---- scratch (device globals; no allocation allowed) ----
__device__ float g_wpack[WPACK_FLOATS];      // rna-converted, fragment-permuted weights
__device__ float g_newh[NCELLS * HID];       // pre-faction-sync new_h
__device__ float g_pfm[NBLK * HID];          // per-block column sums of new_h
__device__ float g_peout[NBLK * OUTD];       // per-block sum of exp(t)*out
__device__ float g_pe[NBLK];                 // per-block sum exp(t)
__device__ float g_pt[NBLK];                 // per-block sum t
__device__ float g_v1[256];                  // v1a[128], v1g[128] = W1[:, :64]@x + b1
__device__ float g_fm[8 * HID];              // faction means
__device__ float g_go[HID];                  // global opinion

__device__ __forceinline__ float sigmoidf_(float v) { return 1.0f / (1.0f + expf(-v)); }

__device__ __forceinline__ float rna_tf32(float x) {
  uint32_t u;
  asm("cvt.rna.tf32.f32 %0, %1;" : "=r"(u) : "f"(x));
  return __uint_as_float(u);
}

__device__ __forceinline__ void mma_tf32(float* d, const uint32_t* a, uint32_t b0, uint32_t b1) {
  asm volatile(
      "mma.sync.aligned.m16n8k8.row.col.f32.tf32.tf32.f32 "
      "{%0,%1,%2,%3}, {%4,%5,%6,%7}, {%8,%9}, {%0,%1,%2,%3};\n"
      : "+f"(d[0]), "+f"(d[1]), "+f"(d[2]), "+f"(d[3])
      : "r"(a[0]), "r"(a[1]), "r"(a[2]), "r"(a[3]), "r"(b0), "r"(b1));
}

// ============================================================================
// kprep: convert weights to rna(tf32) and permute into the smem fragment
// layout: row n, col p where p = 8*(k/8) + (k%8<4 ? 2*(k%8) : 2*(k%8-4)+1).
// B-fragment (b0,b1) = floats (p=8b+2tq, 8b+2tq+1) -> single LDS.64 in k1.
// ============================================================================
__global__ void kprep(const float* __restrict__ W1a, const float* __restrict__ W2a,
                      const float* __restrict__ W1g, const float* __restrict__ W2g,
                      const float* __restrict__ Wih, const float* __restrict__ Whh) {
  int s = blockIdx.y;
  int rows, wp, K, dstoff, ld, co;
  const float* src;
  switch (s) {
    case 0: dstoff = WO_S1;  rows = 128; wp = 132; K = 128; src = W1a;             ld = 192; co = 64; break;
    case 1: dstoff = WO_S2;  rows = 64;  wp = 132; K = 128; src = W2a;             ld = 128; co = 0;  break;
    case 2: dstoff = WO_S3;  rows = 128; wp = 132; K = 128; src = W1g;             ld = 192; co = 64; break;
    case 3: dstoff = WO_S4;  rows = 64;  wp = 132; K = 128; src = W2g;             ld = 128; co = 0;  break;
    case 4: dstoff = WO_S5;  rows = 128; wp = 68;  K = 65;  src = Wih;             ld = 65;  co = 0;  break;
    case 5: dstoff = WO_S6;  rows = 128; wp = 132; K = 128; src = Whh;             ld = 128; co = 0;  break;
    case 6: dstoff = WO_S7;  rows = 128; wp = 68;  K = 65;  src = Wih + 256 * 65;  ld = 65;  co = 0;  break;
    case 7: dstoff = WO_S8;  rows = 128; wp = 132; K = 128; src = Whh + 256 * 128; ld = 128; co = 0;  break;
    case 8: dstoff = WO_S9;  rows = 128; wp = 68;  K = 65;  src = Wih + 128 * 65;  ld = 65;  co = 0;  break;
    default:dstoff = WO_S10; rows = 128; wp = 132; K = 128; src = Whh + 128 * 128; ld = 128; co = 0;  break;
  }
  int e = blockIdx.x * 256 + threadIdx.x;
  if (e >= rows * wp) return;
  int r = e / wp, p = e - r * wp;
  int b = p >> 3, r8 = p & 7;
  int q = (r8 >> 1) + ((r8 & 1) ? 4 : 0);
  int k = b * 8 + q;
  float v = (k < K) ? rna_tf32(src[r * ld + co + k]) : 0.0f;
  g_wpack[dstoff + e] = v;
}

// ============================================================================
// k0: v1a/v1g = W1[:, :64] @ x + b1  (x is shared by all cells) -- fp32 exact
// ============================================================================
__global__ void k0(const float* __restrict__ x,
                   const float* __restrict__ W1a, const float* __restrict__ b1a,
                   const float* __restrict__ W1g, const float* __restrict__ b1g) {
  __shared__ float xs[64];
  int t = threadIdx.x;
  if (t < 64) xs[t] = x[t];
  __syncthreads();
  const float* W = (t < 128) ? W1a : W1g;
  const float* b = (t < 128) ? b1a : b1g;
  int n = t & 127;
  float s = b[n];
#pragma unroll 8
  for (int k = 0; k < 64; k++) s = fmaf(W[n * 192 + k], xs[k], s);
  g_v1[t] = s;
}

// ============================================================================
// mma stage: D[64 cells x N neurons] = A[64 x K] @ W[N x K]^T (+ epilogue)
// Warp (wc = wid/4, wn = wid%4): cells [wc*32, +32), neurons [wn*NT*8, +NT*8).
// MODE: 0 = Y = rna(relu(d+b))          (S1/S3)
//       1 = Y = d+b fp32                (S2)
//       2 = Y -= d+b                    (S4)
//       3 = Y = d+b + t*w64 fp32        (S5/S7/S9, K=65 rank-1 tail)
//       4 = Y = sigmoid(Y + d+b)        (S6: r)
//       5 = Y = tanh(Y + r*(d+b))       (S8: n, r in ACT)
//       6 = z=sig(ACT+d+b); newh=(1-z)*IN + z*H -> gmem + faction partials (S10)
// ============================================================================
template <int K8, int NT, int MODE>
__device__ __forceinline__ void mma_stage(
    float* sm, const float* __restrict__ wsrc, const int wpitch,
    const int abase, const int apitch, const float* __restrict__ bias,
    const int ybase, const int ypitch, const int cell0) {
  const int t = threadIdx.x;
  float* Wb = sm + OFF_W;
  __syncthreads();
  {
    const int nf4 = NT * 32 * (wpitch >> 2);
    const float4* s4 = (const float4*)wsrc;
    float4* d4 = (float4*)Wb;
    for (int i = t; i < nf4; i += BT) d4[i] = s4[i];
  }
  __syncthreads();

  const int lane = t & 31, wid = t >> 5;
  const int wc = wid >> 2, wn = wid & 3;
  const int g = lane >> 2, tq = lane & 3;
  const int c0 = wc * 32;
  const int nb = wn * (NT * 8);

  float d[2][NT][4];
#pragma unroll
  for (int mt = 0; mt < 2; mt++)
#pragma unroll
    for (int nt = 0; nt < NT; nt++)
#pragma unroll
      for (int i = 0; i < 4; i++) d[mt][nt][i] = 0.0f;

  const float* A = sm + abase;
#pragma unroll
  for (int ks = 0; ks < K8; ks++) {
    uint32_t a[2][4];
#pragma unroll
    for (int mt = 0; mt < 2; mt++) {
      const float* ap = A + (c0 + mt * 16 + g) * apitch + ks * 8 + tq;
      a[mt][0] = __float_as_uint(ap[0]);
      a[mt][1] = __float_as_uint(ap[8 * apitch]);
      a[mt][2] = __float_as_uint(ap[4]);
      a[mt][3] = __float_as_uint(ap[8 * apitch + 4]);
    }
#pragma unroll
    for (int nt = 0; nt < NT; nt++) {
      float2 bw = *(const float2*)(Wb + (nb + nt * 8 + g) * wpitch + ks * 8 + 2 * tq);
      uint32_t b0 = __float_as_uint(bw.x), b1 = __float_as_uint(bw.y);
#pragma unroll
      for (int mt = 0; mt < 2; mt++) mma_tf32(d[mt][nt], a[mt], b0, b1);
    }
  }

  // ---------------- epilogue ----------------
  float* Y = sm + ybase;
#pragma unroll
  for (int nt = 0; nt < NT; nt++) {
    const int n = nb + nt * 8 + 2 * tq;
    const float bv0 = bias[n], bv1 = bias[n + 1];
    float w0 = 0.0f, w1 = 0.0f;
    if constexpr (MODE == 3) { w0 = Wb[n * wpitch + 64]; w1 = Wb[(n + 1) * wpitch + 64]; }
    float p0 = 0.0f, p1 = 0.0f;  // MODE 6 faction partials
#pragma unroll
    for (int mt = 0; mt < 2; mt++) {
      const int cA = c0 + mt * 16 + g;
#pragma unroll
      for (int rh = 0; rh < 2; rh++) {
        const int c = cA + rh * 8;
        float v0 = d[mt][nt][rh * 2] + bv0;
        float v1 = d[mt][nt][rh * 2 + 1] + bv1;
        if constexpr (MODE == 3) {
          float tc = sm[OFF_OUT + c * OP + 64];
          v0 = fmaf(tc, w0, v0);
          v1 = fmaf(tc, w1, v1);
        }
        const int yi = c * ypitch + n;
        if constexpr (MODE == 0) {
          Y[yi] = rna_tf32(fmaxf(v0, 0.0f));
          Y[yi + 1] = rna_tf32(fmaxf(v1, 0.0f));
        } else if constexpr (MODE == 1 || MODE == 3) {
          Y[yi] = v0; Y[yi + 1] = v1;
        } else if constexpr (MODE == 2) {
          Y[yi] -= v0; Y[yi + 1] -= v1;
        } else if constexpr (MODE == 4) {
          Y[yi] = sigmoidf_(Y[yi] + v0);
          Y[yi + 1] = sigmoidf_(Y[yi + 1] + v1);
        } else if constexpr (MODE == 5) {
          float r0 = sm[OFF_ACT + c * AP + n], r1 = sm[OFF_ACT + c * AP + n + 1];
          Y[yi] = tanhf(Y[yi] + r0 * v0);
          Y[yi + 1] = tanhf(Y[yi + 1] + r1 * v1);
        } else if constexpr (MODE == 6) {
          float z0 = sigmoidf_(sm[OFF_ACT + c * AP + n] + v0);
          float z1 = sigmoidf_(sm[OFF_ACT + c * AP + n + 1] + v1);
          float n0 = sm[OFF_IN + c * AP + n], n1 = sm[OFF_IN + c * AP + n + 1];
          float h0 = sm[OFF_H + c * AP + n], h1 = sm[OFF_H + c * AP + n + 1];
          float nh0 = (1.0f - z0) * n0 + z0 * h0;
          float nh1 = (1.0f - z1) * n1 + z1 * h1;
          *(float2*)(g_newh + (size_t)(cell0 + c) * HID + n) = make_float2(nh0, nh1);
          p0 += nh0; p1 += nh1;
        }
      }
    }
    if constexpr (MODE == 6) {
      atomicAdd(&sm[OFF_PART + n], p0);
      atomicAdd(&sm[OFF_PART + n + 1], p1);
    }
  }
}

// ============================================================================
// K1: fused engines + tension + GRU per 64-cell tile (tf32 tensor cores)
// ============================================================================
__global__ void __launch_bounds__(BT, 1) k1(
    const float* __restrict__ hiddens,
    const float* __restrict__ b2a, const float* __restrict__ b2g,
    const float* __restrict__ bih, const float* __restrict__ bhh) {
  extern __shared__ float sm[];
  const int t = threadIdx.x;
  const int cell0 = blockIdx.x * TC;

  if (t < 128) sm[OFF_PART + t] = 0.0f;

  // stage h (rna tf32) : [64 cells][128]
  const float4* hsrc = (const float4*)(hiddens + (size_t)cell0 * HID);
  for (int i = t; i < TC * 32; i += BT) {
    int c = i >> 5, q = i & 31;
    float4 v = hsrc[i];
    v.x = rna_tf32(v.x); v.y = rna_tf32(v.y); v.z = rna_tf32(v.z); v.w = rna_tf32(v.w);
    *(float4*)&sm[OFF_H + c * AP + 4 * q] = v;
  }

  // engines (x-part folded into g_v1 bias)
  mma_stage<16, 4, 0>(sm, g_wpack + WO_S1, 132, OFF_H,   AP, g_v1,       OFF_ACT, AP, cell0);
  mma_stage<16, 2, 1>(sm, g_wpack + WO_S2, 132, OFF_ACT, AP, b2a,        OFF_OUT, OP, cell0);
  mma_stage<16, 4, 0>(sm, g_wpack + WO_S3, 132, OFF_H,   AP, g_v1 + 128, OFF_ACT, AP, cell0);
  mma_stage<16, 2, 2>(sm, g_wpack + WO_S4, 132, OFF_ACT, AP, b2g,        OFF_OUT, OP, cell0);
  __syncthreads();

  // tension (fp32 out), pooled softmax partials, then in-place rna conversion
  float* outb = sm + OFF_OUT;
  float* esm = sm + OFF_RED;
  float* tsm = sm + OFF_RED + 64;
  if (t < TC) {
    float s = 0.0f;
#pragma unroll
    for (int n = 0; n < OUTD; n++) { float v = outb[t * OP + n]; s = fmaf(v, v, s); }
    float tc = s * (1.0f / OUTD);
    outb[t * OP + 64] = rna_tf32(tc);
    esm[t] = expf(tc);
    tsm[t] = tc;
  }
  __syncthreads();
  if (t < OUTD) {
    float s = 0.0f;
#pragma unroll
    for (int c = 0; c < TC; c++) s = fmaf(esm[c], outb[c * OP + t], s);
    g_peout[blockIdx.x * OUTD + t] = s;
  }
  if (t == 0) {
    float se = 0.0f, st = 0.0f;
#pragma unroll
    for (int c = 0; c < TC; c++) { se += esm[c]; st += tsm[c]; }
    g_pe[blockIdx.x] = se;
    g_pt[blockIdx.x] = st;
  }
  __syncthreads();
  for (int i = t; i < TC * OUTD; i += BT) {
    int c = i >> 6, n = i & 63;
    outb[c * OP + n] = rna_tf32(outb[c * OP + n]);
  }

  // GRU
  mma_stage<8, 4, 3>(sm, g_wpack + WO_S5,  68,  OFF_OUT, OP, bih,       OFF_ACT, AP, cell0); // ir
  mma_stage<16, 4, 4>(sm, g_wpack + WO_S6, 132, OFF_H,   AP, bhh,       OFF_ACT, AP, cell0); // r
  mma_stage<8, 4, 3>(sm, g_wpack + WO_S7,  68,  OFF_OUT, OP, bih + 256, OFF_IN,  AP, cell0); // i_n
  mma_stage<16, 4, 5>(sm, g_wpack + WO_S8, 132, OFF_H,   AP, bhh + 256, OFF_IN,  AP, cell0); // n
  mma_stage<8, 4, 3>(sm, g_wpack + WO_S9,  68,  OFF_OUT, OP, bih + 128, OFF_ACT, AP, cell0); // iz
  mma_stage<16, 4, 6>(sm, g_wpack + WO_S10,132, OFF_H,   AP, bhh + 128, OFF_ACT, AP, cell0); // z+newh
  __syncthreads();

  if (t < 128) g_pfm[blockIdx.x * HID + t] = sm[OFF_PART + t];
}

// ============================================================================
// K2: fixed-order reductions, faction means, global opinion, pooled head
// ============================================================================
__global__ void __launch_bounds__(256) k2(const float* __restrict__ Wo,
                                          const float* __restrict__ bo,
                                          float* __restrict__ d_out) {
  __shared__ float red[256];
  __shared__ float comb[64];
  __shared__ float sume_s;
  int t = threadIdx.x;

  for (int o = t; o < 8 * HID; o += 256) {
    int f = o >> 7, d = o & 127;
    const float* p = g_pfm + (size_t)f * 256 * HID + d;
    float s = 0.0f;
#pragma unroll 8
    for (int b = 0; b < 256; b++) s += p[b * HID];
    g_fm[o] = s * (1.0f / 16384.0f);
  }
  __syncthreads();
  if (t < HID) {
    float s = 0.0f;
#pragma unroll
    for (int f = 0; f < 8; f++) s += g_fm[f * HID + t];
    g_go[t] = s * 0.125f;
  }

  float se = 0.0f, st = 0.0f;
  for (int b = t; b < NBLK; b += 256) { se += g_pe[b]; st += g_pt[b]; }
  red[t] = se;
  __syncthreads();
  for (int s2 = 128; s2 > 0; s2 >>= 1) { if (t < s2) red[t] += red[t + s2]; __syncthreads(); }
  if (t == 0) sume_s = red[0];
  __syncthreads();
  red[t] = st;
  __syncthreads();
  for (int s2 = 128; s2 > 0; s2 >>= 1) { if (t < s2) red[t] += red[t + s2]; __syncthreads(); }
  if (t == 0) d_out[64] = red[0] * (1.0f / NCELLS);

  if (t < 64) {
    float s = 0.0f;
#pragma unroll 8
    for (int b = 0; b < NBLK; b++) s += g_peout[b * 64 + t];
    comb[t] = s / sume_s;
  }
  __syncthreads();
  if (t < 64) {
    float s = bo[t];
#pragma unroll
    for (int d = 0; d < 64; d++) s = fmaf(Wo[t * 64 + d], comb[d], s);
    d_out[t] = s;
  }
}

// ============================================================================
// K3: apply faction sync + debate, stream to output
// ============================================================================
__global__ void __launch_bounds__(256) k3(const int* __restrict__ step,
                                          float* __restrict__ d_out) {
  int i = blockIdx.x * 256 + threadIdx.x;
  float4 nh = ((const float4*)g_newh)[i];
  int c = i >> 5;
  int dq = i & 31;
  int f = c >> 14;
  float4 fm4 = ((const float4*)g_fm)[f * 32 + dq];
  float4 v;
  v.x = 0.85f * nh.x + 0.15f * fm4.x;
  v.y = 0.85f * nh.y + 0.15f * fm4.y;
  v.z = 0.85f * nh.z + 0.15f * fm4.z;
  v.w = 0.85f * nh.w + 0.15f * fm4.w;
  if (((c & 16383) < 4096) && (*step > 5)) {
    float4 go4 = ((const float4*)g_go)[dq];
    v.x = 0.85f * v.x + 0.15f * go4.x;
    v.y = 0.85f * v.y + 0.15f * go4.y;
    v.z = 0.85f * v.z + 0.15f * go4.z;
    v.w = 0.85f * v.w + 0.15f * go4.w;
  }
  float* o = d_out + 65 + (size_t)i * 4;
  o[0] = v.x; o[1] = v.y; o[2] = v.z; o[3] = v.w;
}

extern "C" void kernel_launch(void* const* d_in, const int* in_sizes, int n_in,
                              void* d_out, int out_size) {
  const float* x    = (const float*)d_in[0];
  const float* hid  = (const float*)d_in[1];
  const float* W1a  = (const float*)d_in[2];
  const float* b1a  = (const float*)d_in[3];
  const float* W2a  = (const float*)d_in[4];
  const float* b2a  = (const float*)d_in[5];
  const float* W1g  = (const float*)d_in[6];
  const float* b1g  = (const float*)d_in[7];
  const float* W2g  = (const float*)d_in[8];
  const float* b2g  = (const float*)d_in[9];
  const float* Wih  = (const float*)d_in[10];
  const float* Whh  = (const float*)d_in[11];
  const float* bih  = (const float*)d_in[12];
  const float* bhh  = (const float*)d_in[13];
  const float* Wo   = (const float*)d_in[14];
  const float* bo   = (const float*)d_in[15];
  const int* step   = (const int*)d_in[16];
  float* out = (float*)d_out;

  cudaFuncSetAttribute(k1, cudaFuncAttributeMaxDynamicSharedMemorySize, SMEM_BYTES);

  kprep<<<dim3(66, 10), 256>>>(W1a, W2a, W1g, W2g, Wih, Whh);
  k0<<<1, 256>>>(x, W1a, b1a, W1g, b1g);
  k1<<<NBLK, BT, SMEM_BYTES>>>(hid, b2a, b2g, bih, bhh);
  k2<<<1, 256>>>(Wo, bo, out);
  k3<<<(NCELLS * HID / 4) / 256, 256>>>(step, out);
}

// round 4
// speedup vs baseline: 2.9335x; 1.4355x over previous
#include <cuda_runtime.h>
#include <math.h>
#include <stdint.h>

#define NCELLS 131072
#define HID 128
#define OUTD 64
#define TC 64                 // cells per block
#define NBLK (NCELLS / TC)    // 2048
#define BT 256                // threads per block (8 warps)

#define AP 132                // pitch for H/B1/B2/B3 (132 % 32 == 4 -> conflict-free)
#define OP 68                 // pitch for OUT

// ---- dynamic smem layout (float offsets) ----
#define OFF_H    0
#define OFF_B1   (OFF_H + 64 * AP)
#define OFF_B2   (OFF_B1 + 64 * AP)
#define OFF_B3   (OFF_B2 + 64 * AP)
#define OFF_OUT  (OFF_B3 + 64 * AP)     // [64][OP], col 64 = t
#define OFF_PART (OFF_OUT + 64 * OP)
#define OFF_RED  (OFF_PART + 128)
#define SMEM_FLOATS (OFF_RED + 128)
#define SMEM_BYTES (SMEM_FLOATS * 4)

// ---- packed weight image offsets (floats) ----
#define PW_W1A 0              // 128 x 128
#define PW_W1G 16384          // 128 x 128
#define PW_W2C 32768          // 64 x 256  ([W2a | -W2g])
#define PW_WIH 49152          // 384 x 64  (rows: ir 0..127, iz 128..255, in 256..383)
#define PW_WHH 73728          // 384 x 128 (rows: hr, hz, hn)
#define WPACK_FLOATS 122880

// ---- scratch (device globals) ----
__device__ float g_wpack[WPACK_FLOATS];
__device__ float g_w64[384];                 // Wih[:,64] (t column)
__device__ float g_newh[NCELLS * HID];
__device__ float g_pfm[NBLK * HID];
__device__ float g_peout[NBLK * OUTD];
__device__ float g_pe[NBLK];
__device__ float g_pt[NBLK];
__device__ float g_v1[256];                  // W1[:, :64]@x + b1 (a then g)
__device__ float g_fm[8 * HID];
__device__ float g_go[HID];

__device__ __forceinline__ float sigmoidf_(float v) { return 1.0f / (1.0f + expf(-v)); }

__device__ __forceinline__ float rna_tf32(float x) {
  uint32_t u;
  asm("cvt.rna.tf32.f32 %0, %1;" : "=r"(u) : "f"(x));
  return __uint_as_float(u);
}

__device__ __forceinline__ void mma_tf32(float* d, const uint32_t* a, uint32_t b0, uint32_t b1) {
  asm volatile(
      "mma.sync.aligned.m16n8k8.row.col.f32.tf32.tf32.f32 "
      "{%0,%1,%2,%3}, {%4,%5,%6,%7}, {%8,%9}, {%0,%1,%2,%3};\n"
      : "+f"(d[0]), "+f"(d[1]), "+f"(d[2]), "+f"(d[3])
      : "r"(a[0]), "r"(a[1]), "r"(a[2]), "r"(a[3]), "r"(b0), "r"(b1));
}

// ============================================================================
// kprep: rna-convert + fragment-permute weights into L2-resident image.
// Within each 8-col block: p = 2*tq (+1) maps to k = tq (tq+4), i.e.
// k = 8*(p/8) + ( (p%8)/2 + 4*((p%8)&1) ).
// ============================================================================
__device__ __forceinline__ int kfp(int p) {
  int b = p >> 3, r8 = p & 7;
  return b * 8 + (r8 >> 1) + ((r8 & 1) << 2);
}

__global__ void kprep(const float* __restrict__ W1a, const float* __restrict__ W2a,
                      const float* __restrict__ W1g, const float* __restrict__ W2g,
                      const float* __restrict__ Wih, const float* __restrict__ Whh) {
  int seg = blockIdx.y;
  int e = blockIdx.x * 256 + threadIdx.x;
  if (seg == 0) {          // W1a hidden part
    if (e >= 16384) return;
    int r = e >> 7, k = kfp(e & 127);
    g_wpack[PW_W1A + e] = rna_tf32(W1a[r * 192 + 64 + k]);
  } else if (seg == 1) {   // W1g hidden part
    if (e >= 16384) return;
    int r = e >> 7, k = kfp(e & 127);
    g_wpack[PW_W1G + e] = rna_tf32(W1g[r * 192 + 64 + k]);
  } else if (seg == 2) {   // [W2a | -W2g]
    if (e >= 16384) return;
    int r = e >> 8, k = kfp(e & 255);
    float v = (k < 128) ? rna_tf32(W2a[r * 128 + k]) : -rna_tf32(W2g[r * 128 + k - 128]);
    g_wpack[PW_W2C + e] = v;
  } else if (seg == 3) {   // Wih cols 0..63
    if (e >= 24576) return;
    int r = e >> 6, k = kfp(e & 63);
    g_wpack[PW_WIH + e] = rna_tf32(Wih[r * 65 + k]);
  } else if (seg == 4) {   // Whh
    if (e >= 49152) return;
    int r = e >> 7, k = kfp(e & 127);
    g_wpack[PW_WHH + e] = rna_tf32(Whh[r * 128 + k]);
  } else {                 // Wih col 64
    if (e >= 384) return;
    g_w64[e] = rna_tf32(Wih[e * 65 + 64]);
  }
}

// ============================================================================
// k0: v1a/v1g = W1[:, :64] @ x + b1 (fp32 exact)
// ============================================================================
__global__ void k0(const float* __restrict__ x,
                   const float* __restrict__ W1a, const float* __restrict__ b1a,
                   const float* __restrict__ W1g, const float* __restrict__ b1g) {
  __shared__ float xs[64];
  int t = threadIdx.x;
  if (t < 64) xs[t] = x[t];
  __syncthreads();
  const float* W = (t < 128) ? W1a : W1g;
  const float* b = (t < 128) ? b1a : b1g;
  int n = t & 127;
  float s = b[n];
#pragma unroll 8
  for (int k = 0; k < 64; k++) s = fmaf(W[n * 192 + k], xs[k], s);
  g_v1[t] = s;
}

// ============================================================================
// mma core: D[64 x N] += A[64 x K] @ W[N x K]^T, B-fragments LDG'd from L2.
// CAT: A = [buf1 | buf2] along K (K8 total chunks, half each).
// ============================================================================
template <int K8, int NT, bool CAT>
__device__ __forceinline__ void mma_core(
    const float* sm, int abase, int apitch, int abase2,
    const float* __restrict__ wg, int wpitch,
    int c0, int nb, int g, int tq, float (&d)[2][NT][4]) {
#pragma unroll
  for (int ks = 0; ks < K8; ks++) {
    int ab = abase, kk = ks;
    if (CAT) { if (ks >= K8 / 2) { ab = abase2; kk = ks - K8 / 2; } }
    uint32_t a[2][4];
#pragma unroll
    for (int mt = 0; mt < 2; mt++) {
      const float* ap = sm + ab + (c0 + mt * 16 + g) * apitch + kk * 8 + tq;
      a[mt][0] = __float_as_uint(ap[0]);
      a[mt][1] = __float_as_uint(ap[8 * apitch]);
      a[mt][2] = __float_as_uint(ap[4]);
      a[mt][3] = __float_as_uint(ap[8 * apitch + 4]);
    }
#pragma unroll
    for (int nt = 0; nt < NT; nt++) {
      float2 bw = *(const float2*)(wg + (size_t)(nb + nt * 8 + g) * wpitch + ks * 8 + 2 * tq);
      uint32_t b0 = __float_as_uint(bw.x), b1 = __float_as_uint(bw.y);
#pragma unroll
      for (int mt = 0; mt < 2; mt++) mma_tf32(d[mt][nt], a[mt], b0, b1);
    }
  }
}

template <int NT>
__device__ __forceinline__ void dzero(float (&d)[2][NT][4]) {
#pragma unroll
  for (int mt = 0; mt < 2; mt++)
#pragma unroll
    for (int nt = 0; nt < NT; nt++)
#pragma unroll
      for (int i = 0; i < 4; i++) d[mt][nt][i] = 0.0f;
}

// ============================================================================
// K1: fused engines + tension + GRU (6 GEMM stages)
// ============================================================================
__global__ void __launch_bounds__(BT, 1) k1(
    const float* __restrict__ hiddens,
    const float* __restrict__ b2a, const float* __restrict__ b2g,
    const float* __restrict__ bih, const float* __restrict__ bhh) {
  extern __shared__ float sm[];
  const int t = threadIdx.x;
  const int cell0 = blockIdx.x * TC;
  const int lane = t & 31, wid = t >> 5;
  const int wc = wid >> 2, wn = wid & 3;
  const int g = lane >> 2, tq = lane & 3;
  const int c0 = wc * 32;

  if (t < 128) sm[OFF_PART + t] = 0.0f;

  // stage h (rna tf32): [64 cells][128] at pitch AP
  const float4* hsrc = (const float4*)(hiddens + (size_t)cell0 * HID);
  for (int i = t; i < TC * 32; i += BT) {
    int c = i >> 5, q = i & 31;
    float4 v = hsrc[i];
    v.x = rna_tf32(v.x); v.y = rna_tf32(v.y); v.z = rna_tf32(v.z); v.w = rna_tf32(v.w);
    *(float4*)&sm[OFF_H + c * AP + 4 * q] = v;
  }

  // ---------------- T1: B1 = rna(relu(H @ W1a^T + v1a)) ----------------
  {
    __syncthreads();
    float d[2][4][4]; dzero<4>(d);
    const int nb = wn * 32;
    mma_core<16, 4, false>(sm, OFF_H, AP, 0, g_wpack + PW_W1A, 128, c0, nb, g, tq, d);
#pragma unroll
    for (int nt = 0; nt < 4; nt++) {
      int n = nb + nt * 8 + 2 * tq;
      float bv0 = g_v1[n], bv1 = g_v1[n + 1];
#pragma unroll
      for (int mt = 0; mt < 2; mt++)
#pragma unroll
        for (int rh = 0; rh < 2; rh++) {
          int c = c0 + mt * 16 + g + rh * 8;
          sm[OFF_B1 + c * AP + n]     = rna_tf32(fmaxf(d[mt][nt][rh * 2] + bv0, 0.0f));
          sm[OFF_B1 + c * AP + n + 1] = rna_tf32(fmaxf(d[mt][nt][rh * 2 + 1] + bv1, 0.0f));
        }
    }
  }

  // ---------------- T2: B2 = rna(relu(H @ W1g^T + v1g)) ----------------
  {
    __syncthreads();
    float d[2][4][4]; dzero<4>(d);
    const int nb = wn * 32;
    mma_core<16, 4, false>(sm, OFF_H, AP, 0, g_wpack + PW_W1G, 128, c0, nb, g, tq, d);
#pragma unroll
    for (int nt = 0; nt < 4; nt++) {
      int n = nb + nt * 8 + 2 * tq;
      float bv0 = g_v1[128 + n], bv1 = g_v1[128 + n + 1];
#pragma unroll
      for (int mt = 0; mt < 2; mt++)
#pragma unroll
        for (int rh = 0; rh < 2; rh++) {
          int c = c0 + mt * 16 + g + rh * 8;
          sm[OFF_B2 + c * AP + n]     = rna_tf32(fmaxf(d[mt][nt][rh * 2] + bv0, 0.0f));
          sm[OFF_B2 + c * AP + n + 1] = rna_tf32(fmaxf(d[mt][nt][rh * 2 + 1] + bv1, 0.0f));
        }
    }
  }

  // ---------------- T3: OUT = [B1|B2] @ [W2a|-W2g]^T + (b2a - b2g) (fp32) ----
  {
    __syncthreads();
    float d[2][2][4]; dzero<2>(d);
    const int nb = wn * 16;
    mma_core<32, 2, true>(sm, OFF_B1, AP, OFF_B2, g_wpack + PW_W2C, 256, c0, nb, g, tq, d);
#pragma unroll
    for (int nt = 0; nt < 2; nt++) {
      int n = nb + nt * 8 + 2 * tq;
      float bv0 = b2a[n] - b2g[n], bv1 = b2a[n + 1] - b2g[n + 1];
#pragma unroll
      for (int mt = 0; mt < 2; mt++)
#pragma unroll
        for (int rh = 0; rh < 2; rh++) {
          int c = c0 + mt * 16 + g + rh * 8;
          sm[OFF_OUT + c * OP + n]     = d[mt][nt][rh * 2] + bv0;
          sm[OFF_OUT + c * OP + n + 1] = d[mt][nt][rh * 2 + 1] + bv1;
        }
    }
  }
  __syncthreads();

  // ---------------- tension + softmax/pool partials ----------------
  {
    float* outb = sm + OFF_OUT;
    float* esm = sm + OFF_RED;
    float* tsm = sm + OFF_RED + 64;
    if (t < TC) {
      float s = 0.0f;
#pragma unroll
      for (int n = 0; n < OUTD; n++) { float v = outb[t * OP + n]; s = fmaf(v, v, s); }
      float tc = s * (1.0f / OUTD);
      outb[t * OP + 64] = rna_tf32(tc);
      esm[t] = expf(tc);
      tsm[t] = tc;
    }
    __syncthreads();
    if (t < OUTD) {
      float s = 0.0f;
#pragma unroll
      for (int c = 0; c < TC; c++) s = fmaf(esm[c], outb[c * OP + t], s);
      g_peout[blockIdx.x * OUTD + t] = s;
    }
    if (t == 0) {
      float se = 0.0f, st = 0.0f;
#pragma unroll
      for (int c = 0; c < TC; c++) { se += esm[c]; st += tsm[c]; }
      g_pe[blockIdx.x] = se;
      g_pt[blockIdx.x] = st;
    }
    __syncthreads();
    for (int i = t; i < TC * OUTD; i += BT) {
      int c = i >> 6, n = i & 63;
      outb[c * OP + n] = rna_tf32(outb[c * OP + n]);
    }
  }

  // ---------------- T4: i-gates (N=384): ir->B1, iz->B3, i_n->B2 ----------
  {
    __syncthreads();
    float d[2][12][4]; dzero<12>(d);
    const int nb = wn * 96;
    mma_core<8, 12, false>(sm, OFF_OUT, OP, 0, g_wpack + PW_WIH, 64, c0, nb, g, tq, d);
#pragma unroll
    for (int nt = 0; nt < 12; nt++) {
      int n = nb + nt * 8 + 2 * tq;
      float bv0 = bih[n], bv1 = bih[n + 1];
      float w0 = g_w64[n], w1 = g_w64[n + 1];
      int base, nc;
      if (n < 128)      { base = OFF_B1; nc = n; }
      else if (n < 256) { base = OFF_B3; nc = n - 128; }
      else              { base = OFF_B2; nc = n - 256; }
#pragma unroll
      for (int mt = 0; mt < 2; mt++)
#pragma unroll
        for (int rh = 0; rh < 2; rh++) {
          int c = c0 + mt * 16 + g + rh * 8;
          float tc = sm[OFF_OUT + c * OP + 64];
          sm[base + c * AP + nc]     = fmaf(tc, w0, d[mt][nt][rh * 2] + bv0);
          sm[base + c * AP + nc + 1] = fmaf(tc, w1, d[mt][nt][rh * 2 + 1] + bv1);
        }
    }
  }

  // ---------------- T5: r = sig(B1 + H@Whh_r^T + bhh_r) -> B1 ; z -> B3 ----
  {
    __syncthreads();
    float d[2][8][4]; dzero<8>(d);
    const int nb = wn * 64;
    mma_core<16, 8, false>(sm, OFF_H, AP, 0, g_wpack + PW_WHH, 128, c0, nb, g, tq, d);
#pragma unroll
    for (int nt = 0; nt < 8; nt++) {
      int n = nb + nt * 8 + 2 * tq;
      float bv0 = bhh[n], bv1 = bhh[n + 1];
      int base = (n < 128) ? OFF_B1 : OFF_B3;
      int nc = (n < 128) ? n : n - 128;
#pragma unroll
      for (int mt = 0; mt < 2; mt++)
#pragma unroll
        for (int rh = 0; rh < 2; rh++) {
          int c = c0 + mt * 16 + g + rh * 8;
          int yi = base + c * AP + nc;
          sm[yi]     = sigmoidf_(sm[yi] + d[mt][nt][rh * 2] + bv0);
          sm[yi + 1] = sigmoidf_(sm[yi + 1] + d[mt][nt][rh * 2 + 1] + bv1);
        }
    }
  }

  // ---------------- T6: n = tanh(B2 + r*(H@Whh_n^T + bhh_n)); newh ----------
  {
    __syncthreads();
    float d[2][4][4]; dzero<4>(d);
    const int nb = wn * 32;
    mma_core<16, 4, false>(sm, OFF_H, AP, 0, g_wpack + PW_WHH + 256 * 128, 128, c0, nb, g, tq, d);
#pragma unroll
    for (int nt = 0; nt < 4; nt++) {
      int n = nb + nt * 8 + 2 * tq;
      float bv0 = bhh[256 + n], bv1 = bhh[256 + n + 1];
      float p0 = 0.0f, p1 = 0.0f;
#pragma unroll
      for (int mt = 0; mt < 2; mt++)
#pragma unroll
        for (int rh = 0; rh < 2; rh++) {
          int c = c0 + mt * 16 + g + rh * 8;
          float r0 = sm[OFF_B1 + c * AP + n],     r1 = sm[OFF_B1 + c * AP + n + 1];
          float z0 = sm[OFF_B3 + c * AP + n],     z1 = sm[OFF_B3 + c * AP + n + 1];
          float i0 = sm[OFF_B2 + c * AP + n],     i1 = sm[OFF_B2 + c * AP + n + 1];
          float h0 = sm[OFF_H + c * AP + n],      h1 = sm[OFF_H + c * AP + n + 1];
          float n0 = tanhf(i0 + r0 * (d[mt][nt][rh * 2] + bv0));
          float n1 = tanhf(i1 + r1 * (d[mt][nt][rh * 2 + 1] + bv1));
          float nh0 = (1.0f - z0) * n0 + z0 * h0;
          float nh1 = (1.0f - z1) * n1 + z1 * h1;
          *(float2*)(g_newh + (size_t)(cell0 + c) * HID + n) = make_float2(nh0, nh1);
          p0 += nh0; p1 += nh1;
        }
      atomicAdd(&sm[OFF_PART + n], p0);
      atomicAdd(&sm[OFF_PART + n + 1], p1);
    }
  }
  __syncthreads();
  if (t < 128) g_pfm[blockIdx.x * HID + t] = sm[OFF_PART + t];
}

// ============================================================================
// K2a: faction means (parallel, coalesced)
// ============================================================================
__global__ void __launch_bounds__(128) k2a() {
  int f = blockIdx.x, d = threadIdx.x;
  const float* p = g_pfm + (size_t)f * 256 * HID + d;
  float s = 0.0f;
#pragma unroll 16
  for (int b = 0; b < 256; b++) s += p[b * HID];
  g_fm[f * HID + d] = s * (1.0f / 16384.0f);
}

// ============================================================================
// K2b: global opinion, scalar reductions, pooled head
// ============================================================================
__global__ void __launch_bounds__(256) k2b(const float* __restrict__ Wo,
                                           const float* __restrict__ bo,
                                           float* __restrict__ d_out) {
  __shared__ float red[256];
  __shared__ float pout[4][64];
  __shared__ float comb[64];
  __shared__ float sume_s;
  int t = threadIdx.x;

  if (t < HID) {
    float s = 0.0f;
#pragma unroll
    for (int f = 0; f < 8; f++) s += g_fm[f * HID + t];
    g_go[t] = s * 0.125f;
  }

  // peout: 256 threads = 64 outputs x 4 chunks of 512 blocks
  {
    int o = t & 63, j = t >> 6;
    const float* p = g_peout + (size_t)j * 512 * 64 + o;
    float s = 0.0f;
#pragma unroll 16
    for (int b = 0; b < 512; b++) s += p[b * 64];
    pout[j][o] = s;
  }

  float se = 0.0f, st = 0.0f;
  for (int b = t; b < NBLK; b += 256) { se += g_pe[b]; st += g_pt[b]; }
  red[t] = se;
  __syncthreads();
  for (int s2 = 128; s2 > 0; s2 >>= 1) { if (t < s2) red[t] += red[t + s2]; __syncthreads(); }
  if (t == 0) sume_s = red[0];
  __syncthreads();
  red[t] = st;
  __syncthreads();
  for (int s2 = 128; s2 > 0; s2 >>= 1) { if (t < s2) red[t] += red[t + s2]; __syncthreads(); }
  if (t == 0) d_out[64] = red[0] * (1.0f / NCELLS);

  if (t < 64) comb[t] = (((pout[0][t] + pout[1][t]) + pout[2][t]) + pout[3][t]) / sume_s;
  __syncthreads();
  if (t < 64) {
    float s = bo[t];
#pragma unroll
    for (int d = 0; d < 64; d++) s = fmaf(Wo[t * 64 + d], comb[d], s);
    d_out[t] = s;
  }
}

// ============================================================================
// K3: apply faction sync + debate, stream to output
// ============================================================================
__global__ void __launch_bounds__(256) k3(const int* __restrict__ step,
                                          float* __restrict__ d_out) {
  int i = blockIdx.x * 256 + threadIdx.x;
  float4 nh = ((const float4*)g_newh)[i];
  int c = i >> 5;
  int dq = i & 31;
  int f = c >> 14;
  float4 fm4 = ((const float4*)g_fm)[f * 32 + dq];
  float4 v;
  v.x = 0.85f * nh.x + 0.15f * fm4.x;
  v.y = 0.85f * nh.y + 0.15f * fm4.y;
  v.z = 0.85f * nh.z + 0.15f * fm4.z;
  v.w = 0.85f * nh.w + 0.15f * fm4.w;
  if (((c & 16383) < 4096) && (*step > 5)) {
    float4 go4 = ((const float4*)g_go)[dq];
    v.x = 0.85f * v.x + 0.15f * go4.x;
    v.y = 0.85f * v.y + 0.15f * go4.y;
    v.z = 0.85f * v.z + 0.15f * go4.z;
    v.w = 0.85f * v.w + 0.15f * go4.w;
  }
  float* o = d_out + 65 + (size_t)i * 4;
  o[0] = v.x; o[1] = v.y; o[2] = v.z; o[3] = v.w;
}

extern "C" void kernel_launch(void* const* d_in, const int* in_sizes, int n_in,
                              void* d_out, int out_size) {
  const float* x    = (const float*)d_in[0];
  const float* hid  = (const float*)d_in[1];
  const float* W1a  = (const float*)d_in[2];
  const float* b1a  = (const float*)d_in[3];
  const float* W2a  = (const float*)d_in[4];
  const float* b2a  = (const float*)d_in[5];
  const float* W1g  = (const float*)d_in[6];
  const float* b1g  = (const float*)d_in[7];
  const float* W2g  = (const float*)d_in[8];
  const float* b2g  = (const float*)d_in[9];
  const float* Wih  = (const float*)d_in[10];
  const float* Whh  = (const float*)d_in[11];
  const float* bih  = (const float*)d_in[12];
  const float* bhh  = (const float*)d_in[13];
  const float* Wo   = (const float*)d_in[14];
  const float* bo   = (const float*)d_in[15];
  const int* step   = (const int*)d_in[16];
  float* out = (float*)d_out;

  cudaFuncSetAttribute(k1, cudaFuncAttributeMaxDynamicSharedMemorySize, SMEM_BYTES);

  kprep<<<dim3(192, 6), 256>>>(W1a, W2a, W1g, W2g, Wih, Whh);
  k0<<<1, 256>>>(x, W1a, b1a, W1g, b1g);
  k1<<<NBLK, BT, SMEM_BYTES>>>(hid, b2a, b2g, bih, bhh);
  k2a<<<8, 128>>>();
  k2b<<<1, 256>>>(Wo, bo, out);
  k3<<<(NCELLS * HID / 4) / 256, 256>>>(step, out);
}

// round 5
// speedup vs baseline: 3.3415x; 1.1391x over previous
#include <cuda_runtime.h>
#include <math.h>
#include <stdint.h>

#define NCELLS 131072
#define HID 128
#define OUTD 64
#define TC 64                 // cells per block
#define NBLK (NCELLS / TC)    // 2048
#define BT 512                // threads per block (16 warps)

#define AP 132                // pitch for H/B1/B2/B3 (mod 32 == 4 -> conflict-free)
#define OP 68                 // pitch for OUT

// ---- dynamic smem layout (float offsets) ----
#define OFF_H    0
#define OFF_B1   (OFF_H + 64 * AP)
#define OFF_B2   (OFF_B1 + 64 * AP)
#define OFF_B3   (OFF_B2 + 64 * AP)
#define OFF_OUT  (OFF_B3 + 64 * AP)     // [64][OP], col 64 = t
#define OFF_PART (OFF_OUT + 64 * OP)
#define OFF_RED  (OFF_PART + 128)
#define SMEM_FLOATS (OFF_RED + 128)
#define SMEM_BYTES (SMEM_FLOATS * 4)

// ---- packed weight image offsets (floats) ----
#define PW_W1A 0              // 128 x 128   (rows 0..127)
#define PW_W1G 16384          // 128 x 128   (rows 128..255 of the same image)
#define PW_W2C 32768          // 64 x 256    ([W2a | -W2g])
#define PW_WIH 49152          // 384 x 64    (rows: ir, iz, i_n)
#define PW_WHH 73728          // 384 x 128   (rows: hr, hz, hn)
#define WPACK_FLOATS 122880

// ---- scratch (device globals) ----
__device__ float g_wpack[WPACK_FLOATS];
__device__ float g_w64[384];                 // Wih[:,64] (t column)
__device__ float g_newh[NCELLS * HID];
__device__ float g_pfm[NBLK * HID];
__device__ float g_peout[NBLK * OUTD];
__device__ float g_pe[NBLK];
__device__ float g_pt[NBLK];
__device__ float g_v1[256];                  // W1[:, :64]@x + b1 (a then g)
__device__ float g_fm[8 * HID];
__device__ float g_go[HID];

__device__ __forceinline__ float sigmoidf_(float v) { return 1.0f / (1.0f + expf(-v)); }

__device__ __forceinline__ float rna_tf32(float x) {
  uint32_t u;
  asm("cvt.rna.tf32.f32 %0, %1;" : "=r"(u) : "f"(x));
  return __uint_as_float(u);
}

__device__ __forceinline__ void mma_tf32(float* d, const uint32_t* a, uint32_t b0, uint32_t b1) {
  asm volatile(
      "mma.sync.aligned.m16n8k8.row.col.f32.tf32.tf32.f32 "
      "{%0,%1,%2,%3}, {%4,%5,%6,%7}, {%8,%9}, {%0,%1,%2,%3};\n"
      : "+f"(d[0]), "+f"(d[1]), "+f"(d[2]), "+f"(d[3])
      : "r"(a[0]), "r"(a[1]), "r"(a[2]), "r"(a[3]), "r"(b0), "r"(b1));
}

// ============================================================================
// kprep: rna-convert + fragment-permute weights into L2-resident image.
// Within each 8-col block: k = 8*(p/8) + ((p%8)/2 + 4*((p%8)&1)).
// ============================================================================
__device__ __forceinline__ int kfp(int p) {
  int b = p >> 3, r8 = p & 7;
  return b * 8 + (r8 >> 1) + ((r8 & 1) << 2);
}

__global__ void kprep(const float* __restrict__ W1a, const float* __restrict__ W2a,
                      const float* __restrict__ W1g, const float* __restrict__ W2g,
                      const float* __restrict__ Wih, const float* __restrict__ Whh) {
  int seg = blockIdx.y;
  int e = blockIdx.x * 256 + threadIdx.x;
  if (seg == 0) {          // W1a hidden part
    if (e >= 16384) return;
    int r = e >> 7, k = kfp(e & 127);
    g_wpack[PW_W1A + e] = rna_tf32(W1a[r * 192 + 64 + k]);
  } else if (seg == 1) {   // W1g hidden part
    if (e >= 16384) return;
    int r = e >> 7, k = kfp(e & 127);
    g_wpack[PW_W1G + e] = rna_tf32(W1g[r * 192 + 64 + k]);
  } else if (seg == 2) {   // [W2a | -W2g]
    if (e >= 16384) return;
    int r = e >> 8, k = kfp(e & 255);
    float v = (k < 128) ? rna_tf32(W2a[r * 128 + k]) : -rna_tf32(W2g[r * 128 + k - 128]);
    g_wpack[PW_W2C + e] = v;
  } else if (seg == 3) {   // Wih cols 0..63
    if (e >= 24576) return;
    int r = e >> 6, k = kfp(e & 63);
    g_wpack[PW_WIH + e] = rna_tf32(Wih[r * 65 + k]);
  } else if (seg == 4) {   // Whh
    if (e >= 49152) return;
    int r = e >> 7, k = kfp(e & 127);
    g_wpack[PW_WHH + e] = rna_tf32(Whh[r * 128 + k]);
  } else {                 // Wih col 64
    if (e >= 384) return;
    g_w64[e] = rna_tf32(Wih[e * 65 + 64]);
  }
}

// ============================================================================
// k0: v1a/v1g = W1[:, :64] @ x + b1 (fp32 exact)
// ============================================================================
__global__ void k0(const float* __restrict__ x,
                   const float* __restrict__ W1a, const float* __restrict__ b1a,
                   const float* __restrict__ W1g, const float* __restrict__ b1g) {
  __shared__ float xs[64];
  int t = threadIdx.x;
  if (t < 64) xs[t] = x[t];
  __syncthreads();
  const float* W = (t < 128) ? W1a : W1g;
  const float* b = (t < 128) ? b1a : b1g;
  int n = t & 127;
  float s = b[n];
#pragma unroll 8
  for (int k = 0; k < 64; k++) s = fmaf(W[n * 192 + k], xs[k], s);
  g_v1[t] = s;
}

// kdummy: placeholder so ncu's fixed capture index lands on k1.
__global__ void kdummy() {}

// ============================================================================
// mma core with software-pipelined B-fragment prefetch (B from L2 via LDG).
// CAT: A = [buf1 | buf2] along K (K8 total chunks, half each).
// ============================================================================
template <int K8, int NT, bool CAT>
__device__ __forceinline__ void mma_core(
    const float* sm, int abase, int apitch, int abase2,
    const float* __restrict__ wg, int wpitch,
    int c0, int nb, int g, int tq, float (&d)[2][NT][4]) {
  const float* wbase = wg + (size_t)(nb + g) * wpitch + 2 * tq;
  float2 bf[NT];
#pragma unroll
  for (int nt = 0; nt < NT; nt++)
    bf[nt] = *(const float2*)(wbase + (size_t)nt * 8 * wpitch);
#pragma unroll
  for (int ks = 0; ks < K8; ks++) {
    int ab = abase, kk = ks;
    if (CAT) { if (ks >= K8 / 2) { ab = abase2; kk = ks - K8 / 2; } }
    uint32_t a[2][4];
#pragma unroll
    for (int mt = 0; mt < 2; mt++) {
      const float* ap = sm + ab + (c0 + mt * 16 + g) * apitch + kk * 8 + tq;
      a[mt][0] = __float_as_uint(ap[0]);
      a[mt][1] = __float_as_uint(ap[8 * apitch]);
      a[mt][2] = __float_as_uint(ap[4]);
      a[mt][3] = __float_as_uint(ap[8 * apitch + 4]);
    }
    float2 bn[NT];
    if (ks + 1 < K8) {
#pragma unroll
      for (int nt = 0; nt < NT; nt++)
        bn[nt] = *(const float2*)(wbase + (size_t)nt * 8 * wpitch + (ks + 1) * 8);
    }
#pragma unroll
    for (int nt = 0; nt < NT; nt++) {
      uint32_t b0 = __float_as_uint(bf[nt].x), b1 = __float_as_uint(bf[nt].y);
#pragma unroll
      for (int mt = 0; mt < 2; mt++) mma_tf32(d[mt][nt], a[mt], b0, b1);
    }
    if (ks + 1 < K8) {
#pragma unroll
      for (int nt = 0; nt < NT; nt++) bf[nt] = bn[nt];
    }
  }
}

template <int NT>
__device__ __forceinline__ void dzero(float (&d)[2][NT][4]) {
#pragma unroll
  for (int mt = 0; mt < 2; mt++)
#pragma unroll
    for (int nt = 0; nt < NT; nt++)
#pragma unroll
      for (int i = 0; i < 4; i++) d[mt][nt][i] = 0.0f;
}

// ============================================================================
// K1: fused engines + tension + GRU (5 GEMM stages, 16 warps)
// Warp tiling: wc = wid>>3 (cell half), wn = wid&7 (n-group).
// ============================================================================
__global__ void __launch_bounds__(BT, 1) k1(
    const float* __restrict__ hiddens,
    const float* __restrict__ b2a, const float* __restrict__ b2g,
    const float* __restrict__ bih, const float* __restrict__ bhh) {
  extern __shared__ float sm[];
  const int t = threadIdx.x;
  const int cell0 = blockIdx.x * TC;
  const int lane = t & 31, wid = t >> 5;
  const int wc = wid >> 3, wn = wid & 7;
  const int g = lane >> 2, tq = lane & 3;
  const int c0 = wc * 32;

  if (t < 128) sm[OFF_PART + t] = 0.0f;

  // stage h (rna tf32): [64 cells][128] at pitch AP
  const float4* hsrc = (const float4*)(hiddens + (size_t)cell0 * HID);
  for (int i = t; i < TC * 32; i += BT) {
    int c = i >> 5, q = i & 31;
    float4 v = hsrc[i];
    v.x = rna_tf32(v.x); v.y = rna_tf32(v.y); v.z = rna_tf32(v.z); v.w = rna_tf32(v.w);
    *(float4*)&sm[OFF_H + c * AP + 4 * q] = v;
  }

  // ---------------- T12: [relu_a | relu_g] = relu(H @ [W1a;W1g]^T + v1) ------
  {
    __syncthreads();
    float d[2][4][4]; dzero<4>(d);
    const int nb = wn * 32;                 // n in 0..255
    mma_core<16, 4, false>(sm, OFF_H, AP, 0, g_wpack + PW_W1A, 128, c0, nb, g, tq, d);
#pragma unroll
    for (int nt = 0; nt < 4; nt++) {
      int n = nb + nt * 8 + 2 * tq;
      int base = (n < 128) ? OFF_B1 : OFF_B2;
      int nc = n & 127;
      float bv0 = g_v1[n], bv1 = g_v1[n + 1];
#pragma unroll
      for (int mt = 0; mt < 2; mt++)
#pragma unroll
        for (int rh = 0; rh < 2; rh++) {
          int c = c0 + mt * 16 + g + rh * 8;
          sm[base + c * AP + nc]     = rna_tf32(fmaxf(d[mt][nt][rh * 2] + bv0, 0.0f));
          sm[base + c * AP + nc + 1] = rna_tf32(fmaxf(d[mt][nt][rh * 2 + 1] + bv1, 0.0f));
        }
    }
  }

  // ---------------- T3: OUT = [B1|B2] @ [W2a|-W2g]^T + (b2a-b2g) (fp32) ------
  {
    __syncthreads();
    float d[2][1][4]; dzero<1>(d);
    const int nb = wn * 8;                  // n in 0..63
    mma_core<32, 1, true>(sm, OFF_B1, AP, OFF_B2, g_wpack + PW_W2C, 256, c0, nb, g, tq, d);
    {
      int n = nb + 2 * tq;
      float bv0 = b2a[n] - b2g[n], bv1 = b2a[n + 1] - b2g[n + 1];
#pragma unroll
      for (int mt = 0; mt < 2; mt++)
#pragma unroll
        for (int rh = 0; rh < 2; rh++) {
          int c = c0 + mt * 16 + g + rh * 8;
          sm[OFF_OUT + c * OP + n]     = d[mt][0][rh * 2] + bv0;
          sm[OFF_OUT + c * OP + n + 1] = d[mt][0][rh * 2 + 1] + bv1;
        }
    }
  }
  __syncthreads();

  // ---------------- tension + softmax/pool partials ----------------
  {
    float* outb = sm + OFF_OUT;
    float* esm = sm + OFF_RED;
    float* tsm = sm + OFF_RED + 64;
    if (t < TC) {
      float s = 0.0f;
#pragma unroll
      for (int n = 0; n < OUTD; n++) { float v = outb[t * OP + n]; s = fmaf(v, v, s); }
      float tc = s * (1.0f / OUTD);
      outb[t * OP + 64] = rna_tf32(tc);
      esm[t] = expf(tc);
      tsm[t] = tc;
    }
    __syncthreads();
    if (t < OUTD) {
      float s = 0.0f;
#pragma unroll
      for (int c = 0; c < TC; c++) s = fmaf(esm[c], outb[c * OP + t], s);
      g_peout[blockIdx.x * OUTD + t] = s;
    }
    if (t == 0) {
      float se = 0.0f, st = 0.0f;
#pragma unroll
      for (int c = 0; c < TC; c++) { se += esm[c]; st += tsm[c]; }
      g_pe[blockIdx.x] = se;
      g_pt[blockIdx.x] = st;
    }
    __syncthreads();
    for (int i = t; i < TC * OUTD; i += BT) {
      int c = i >> 6, n = i & 63;
      outb[c * OP + n] = rna_tf32(outb[c * OP + n]);
    }
  }

  // ---------------- T4: i-gates (N=384): ir->B1, iz->B3, i_n->B2 ------------
  {
    __syncthreads();
    float d[2][6][4]; dzero<6>(d);
    const int nb = wn * 48;                 // n in 0..383
    mma_core<8, 6, false>(sm, OFF_OUT, OP, 0, g_wpack + PW_WIH, 64, c0, nb, g, tq, d);
#pragma unroll
    for (int nt = 0; nt < 6; nt++) {
      int n = nb + nt * 8 + 2 * tq;
      float bv0 = bih[n], bv1 = bih[n + 1];
      float w0 = g_w64[n], w1 = g_w64[n + 1];
      int base, nc;
      if (n < 128)      { base = OFF_B1; nc = n; }
      else if (n < 256) { base = OFF_B3; nc = n - 128; }
      else              { base = OFF_B2; nc = n - 256; }
#pragma unroll
      for (int mt = 0; mt < 2; mt++)
#pragma unroll
        for (int rh = 0; rh < 2; rh++) {
          int c = c0 + mt * 16 + g + rh * 8;
          float tc = sm[OFF_OUT + c * OP + 64];
          sm[base + c * AP + nc]     = fmaf(tc, w0, d[mt][nt][rh * 2] + bv0);
          sm[base + c * AP + nc + 1] = fmaf(tc, w1, d[mt][nt][rh * 2 + 1] + bv1);
        }
    }
  }

  // ---------------- T5: r = sig(B1 + H@Whh_r^T + bhh_r); z -> B3 ------------
  {
    __syncthreads();
    float d[2][4][4]; dzero<4>(d);
    const int nb = wn * 32;                 // n in 0..255
    mma_core<16, 4, false>(sm, OFF_H, AP, 0, g_wpack + PW_WHH, 128, c0, nb, g, tq, d);
#pragma unroll
    for (int nt = 0; nt < 4; nt++) {
      int n = nb + nt * 8 + 2 * tq;
      float bv0 = bhh[n], bv1 = bhh[n + 1];
      int base = (n < 128) ? OFF_B1 : OFF_B3;
      int nc = n & 127;
#pragma unroll
      for (int mt = 0; mt < 2; mt++)
#pragma unroll
        for (int rh = 0; rh < 2; rh++) {
          int c = c0 + mt * 16 + g + rh * 8;
          int yi = base + c * AP + nc;
          sm[yi]     = sigmoidf_(sm[yi] + d[mt][nt][rh * 2] + bv0);
          sm[yi + 1] = sigmoidf_(sm[yi + 1] + d[mt][nt][rh * 2 + 1] + bv1);
        }
    }
  }

  // ---------------- T6: n = tanh(B2 + r*(H@Whh_n^T + bhh_n)); newh ----------
  {
    __syncthreads();
    float d[2][2][4]; dzero<2>(d);
    const int nb = wn * 16;                 // n in 0..127
    mma_core<16, 2, false>(sm, OFF_H, AP, 0, g_wpack + PW_WHH + 256 * 128, 128, c0, nb, g, tq, d);
#pragma unroll
    for (int nt = 0; nt < 2; nt++) {
      int n = nb + nt * 8 + 2 * tq;
      float bv0 = bhh[256 + n], bv1 = bhh[256 + n + 1];
      float p0 = 0.0f, p1 = 0.0f;
#pragma unroll
      for (int mt = 0; mt < 2; mt++)
#pragma unroll
        for (int rh = 0; rh < 2; rh++) {
          int c = c0 + mt * 16 + g + rh * 8;
          float r0 = sm[OFF_B1 + c * AP + n],     r1 = sm[OFF_B1 + c * AP + n + 1];
          float z0 = sm[OFF_B3 + c * AP + n],     z1 = sm[OFF_B3 + c * AP + n + 1];
          float i0 = sm[OFF_B2 + c * AP + n],     i1 = sm[OFF_B2 + c * AP + n + 1];
          float h0 = sm[OFF_H + c * AP + n],      h1 = sm[OFF_H + c * AP + n + 1];
          float n0 = tanhf(i0 + r0 * (d[mt][nt][rh * 2] + bv0));
          float n1 = tanhf(i1 + r1 * (d[mt][nt][rh * 2 + 1] + bv1));
          float nh0 = (1.0f - z0) * n0 + z0 * h0;
          float nh1 = (1.0f - z1) * n1 + z1 * h1;
          *(float2*)(g_newh + (size_t)(cell0 + c) * HID + n) = make_float2(nh0, nh1);
          p0 += nh0; p1 += nh1;
        }
      atomicAdd(&sm[OFF_PART + n], p0);
      atomicAdd(&sm[OFF_PART + n + 1], p1);
    }
  }
  __syncthreads();
  if (t < 128) g_pfm[blockIdx.x * HID + t] = sm[OFF_PART + t];
}

// ============================================================================
// K2a: faction means (parallel, coalesced)
// ============================================================================
__global__ void __launch_bounds__(128) k2a() {
  int f = blockIdx.x, d = threadIdx.x;
  const float* p = g_pfm + (size_t)f * 256 * HID + d;
  float s = 0.0f;
#pragma unroll 16
  for (int b = 0; b < 256; b++) s += p[b * HID];
  g_fm[f * HID + d] = s * (1.0f / 16384.0f);
}

// ============================================================================
// K2b: global opinion, scalar reductions, pooled head
// ============================================================================
__global__ void __launch_bounds__(256) k2b(const float* __restrict__ Wo,
                                           const float* __restrict__ bo,
                                           float* __restrict__ d_out) {
  __shared__ float red[256];
  __shared__ float pout[4][64];
  __shared__ float comb[64];
  __shared__ float sume_s;
  int t = threadIdx.x;

  if (t < HID) {
    float s = 0.0f;
#pragma unroll
    for (int f = 0; f < 8; f++) s += g_fm[f * HID + t];
    g_go[t] = s * 0.125f;
  }

  {
    int o = t & 63, j = t >> 6;
    const float* p = g_peout + (size_t)j * 512 * 64 + o;
    float s = 0.0f;
#pragma unroll 16
    for (int b = 0; b < 512; b++) s += p[b * 64];
    pout[j][o] = s;
  }

  float se = 0.0f, st = 0.0f;
  for (int b = t; b < NBLK; b += 256) { se += g_pe[b]; st += g_pt[b]; }
  red[t] = se;
  __syncthreads();
  for (int s2 = 128; s2 > 0; s2 >>= 1) { if (t < s2) red[t] += red[t + s2]; __syncthreads(); }
  if (t == 0) sume_s = red[0];
  __syncthreads();
  red[t] = st;
  __syncthreads();
  for (int s2 = 128; s2 > 0; s2 >>= 1) { if (t < s2) red[t] += red[t + s2]; __syncthreads(); }
  if (t == 0) d_out[64] = red[0] * (1.0f / NCELLS);

  if (t < 64) comb[t] = (((pout[0][t] + pout[1][t]) + pout[2][t]) + pout[3][t]) / sume_s;
  __syncthreads();
  if (t < 64) {
    float s = bo[t];
#pragma unroll
    for (int d = 0; d < 64; d++) s = fmaf(Wo[t * 64 + d], comb[d], s);
    d_out[t] = s;
  }
}

// ============================================================================
// K3: apply faction sync + debate, stream to output
// ============================================================================
__global__ void __launch_bounds__(256) k3(const int* __restrict__ step,
                                          float* __restrict__ d_out) {
  int i = blockIdx.x * 256 + threadIdx.x;
  float4 nh = ((const float4*)g_newh)[i];
  int c = i >> 5;
  int dq = i & 31;
  int f = c >> 14;
  float4 fm4 = ((const float4*)g_fm)[f * 32 + dq];
  float4 v;
  v.x = 0.85f * nh.x + 0.15f * fm4.x;
  v.y = 0.85f * nh.y + 0.15f * fm4.y;
  v.z = 0.85f * nh.z + 0.15f * fm4.z;
  v.w = 0.85f * nh.w + 0.15f * fm4.w;
  if (((c & 16383) < 4096) && (*step > 5)) {
    float4 go4 = ((const float4*)g_go)[dq];
    v.x = 0.85f * v.x + 0.15f * go4.x;
    v.y = 0.85f * v.y + 0.15f * go4.y;
    v.z = 0.85f * v.z + 0.15f * go4.z;
    v.w = 0.85f * v.w + 0.15f * go4.w;
  }
  float* o = d_out + 65 + (size_t)i * 4;
  o[0] = v.x; o[1] = v.y; o[2] = v.z; o[3] = v.w;
}

extern "C" void kernel_launch(void* const* d_in, const int* in_sizes, int n_in,
                              void* d_out, int out_size) {
  const float* x    = (const float*)d_in[0];
  const float* hid  = (const float*)d_in[1];
  const float* W1a  = (const float*)d_in[2];
  const float* b1a  = (const float*)d_in[3];
  const float* W2a  = (const float*)d_in[4];
  const float* b2a  = (const float*)d_in[5];
  const float* W1g  = (const float*)d_in[6];
  const float* b1g  = (const float*)d_in[7];
  const float* W2g  = (const float*)d_in[8];
  const float* b2g  = (const float*)d_in[9];
  const float* Wih  = (const float*)d_in[10];
  const float* Whh  = (const float*)d_in[11];
  const float* bih  = (const float*)d_in[12];
  const float* bhh  = (const float*)d_in[13];
  const float* Wo   = (const float*)d_in[14];
  const float* bo   = (const float*)d_in[15];
  const int* step   = (const int*)d_in[16];
  float* out = (float*)d_out;

  cudaFuncSetAttribute(k1, cudaFuncAttributeMaxDynamicSharedMemorySize, SMEM_BYTES);

  kprep<<<dim3(192, 6), 256>>>(W1a, W2a, W1g, W2g, Wih, Whh);      // launch 0
  k0<<<1, 256>>>(x, W1a, b1a, W1g, b1g);                           // launch 1
  kdummy<<<1, 32>>>();                                             // launch 2 (capture pad)
  k1<<<NBLK, BT, SMEM_BYTES>>>(hid, b2a, b2g, bih, bhh);           // launch 3 <- ncu
  k2a<<<8, 128>>>();                                               // launch 4
  k2b<<<1, 256>>>(Wo, bo, out);                                    // launch 5
  k3<<<(NCELLS * HID / 4) / 256, 256>>>(step, out);                // launch 6
}